// round 8
// baseline (speedup 1.0000x reference)
#include <cuda_runtime.h>
#include <cuda_bf16.h>
#include <cstdint>

// LoRA low-rank, 3-kernel pipeline (round 7 = R4 + targeted fixes):
//   prep   : At[k][r] = 2 * A[r][k]
//   phase1 : tp[ks][m][r] = sum_{k in slice} x[m][k] * At[k][r]
//            2 m/lane (32 acc regs), full-line LDG, conflict-free pitch-65
//            transpose, occupancy 3.
//   phase2 : out[m][o] = sum_r (sum_ks tp) * B[o][r] + bias[o]
//            B in registers, t broadcast; 2-m unroll (4 ILP chains).

#define IN_F   4096
#define OUT_F  4096
#define RANK   16
#define M_TOT  8192

#define KSPLIT 8
#define KRANGE (IN_F / KSPLIT)    // 512
#define MT     64                 // m rows per phase-1 block
#define KC     64                 // k chunk staged in smem
#define NCH    (KRANGE / KC)      // 8
#define XP     65                 // xs pitch: conflict-free both directions

#define OTPB   1024               // o columns per phase-2 block
#define MSLAB  128                // m rows per phase-2 block

__device__ __align__(16) float g_At[IN_F * RANK];            // 256 KB
__device__ __align__(16) float g_tp[KSPLIT][M_TOT][RANK];    // 4 MB partials

typedef unsigned long long u64;

__device__ __forceinline__ u64 pk2(float lo, float hi) {
    u64 r; asm("mov.b64 %0, {%1,%2};" : "=l"(r) : "f"(lo), "f"(hi)); return r;
}
__device__ __forceinline__ void fma2(u64 &d, u64 a, u64 b) {
    asm("fma.rn.f32x2 %0, %1, %2, %0;" : "+l"(d) : "l"(a), "l"(b));
}
__device__ __forceinline__ float2 up2(u64 v) {
    float2 f; asm("mov.b64 {%0,%1}, %2;" : "=f"(f.x), "=f"(f.y) : "l"(v)); return f;
}

// ---------------- prep: At = 2*A^T, coalesced STG.128 ----------------
__global__ void prep_At(const float* __restrict__ A) {
    const int i  = blockIdx.x * 256 + threadIdx.x;   // 16384
    const int k  = i >> 2;
    const int rq = i & 3;
    float4 v;
    v.x = 2.0f * A[(size_t)(4 * rq + 0) * IN_F + k];
    v.y = 2.0f * A[(size_t)(4 * rq + 1) * IN_F + k];
    v.z = 2.0f * A[(size_t)(4 * rq + 2) * IN_F + k];
    v.w = 2.0f * A[(size_t)(4 * rq + 3) * IN_F + k];
    ((float4*)g_At)[k * 4 + rq] = v;
}

// ---------------- phase 1 ----------------
// smem: [0,33280) xs[2][KC][XP] floats ; [33280,41472) as4[2][KC*4] float4
//       tredf[8][64][16] floats (32768 B) aliases xs after the k-loop.
__global__ __launch_bounds__(256, 3)
void lora_phase1(const float* __restrict__ x) {
    __shared__ __align__(16) char sraw[41472];
    float*  xs    = (float*)sraw;
    float4* as4   = (float4*)(sraw + 33280);
    float*  tredf = (float*)sraw;

    const int tid  = threadIdx.x;
    const int lane = tid & 31;
    const int w    = tid >> 5;                  // 8 warps
    const int ks   = blockIdx.x & (KSPLIT - 1);
    const int mt   = blockIdx.x >> 3;           // 0..127
    const int mbase = mt * MT;
    const int k0    = ks * KRANGE;

    // full-line LDG mapping: lanes 0..7 cover one whole 128B line of a row
    const int lm = tid >> 3;                    // 0..31 (row in 32-row group)
    const int lc = (tid & 7) * 4;               // col floats within 32-col half
    const float* xg = x + (size_t)(mbase + lm) * IN_F + k0 + lc;

    u64 acc[2][8];
    #pragma unroll
    for (int mp = 0; mp < 2; ++mp)
        #pragma unroll
        for (int rp = 0; rp < 8; ++rp) acc[mp][rp] = 0ull;

    float4 xr[2][2], ar;

    // prologue: chunk 0 (rows lm, lm+32; col halves lc, lc+32)
    #pragma unroll
    for (int i = 0; i < 2; ++i)
        #pragma unroll
        for (int j = 0; j < 2; ++j)
            xr[i][j] = *(const float4*)(xg + (size_t)(32 * i) * IN_F + 32 * j);
    ar = ((const float4*)g_At)[k0 * 4 + tid];

    #pragma unroll
    for (int i = 0; i < 2; ++i)
        #pragma unroll
        for (int j = 0; j < 2; ++j) {
            const int m = lm + 32 * i;
            const int c = lc + 32 * j;
            xs[(c + 0) * XP + m] = xr[i][j].x;
            xs[(c + 1) * XP + m] = xr[i][j].y;
            xs[(c + 2) * XP + m] = xr[i][j].z;
            xs[(c + 3) * XP + m] = xr[i][j].w;
        }
    as4[tid] = ar;
    __syncthreads();

    for (int c = 0; c < NCH; ++c) {
        const int buf = c & 1;

        if (c + 1 < NCH) {                      // prefetch chunk c+1
            const int kc1 = (c + 1) * KC;
            #pragma unroll
            for (int i = 0; i < 2; ++i)
                #pragma unroll
                for (int j = 0; j < 2; ++j)
                    xr[i][j] = *(const float4*)(xg + kc1 + (size_t)(32 * i) * IN_F + 32 * j);
            ar = ((const float4*)g_At)[(k0 + kc1) * 4 + tid];
        }

        // compute: warp w covers k = w*8 .. w*8+7 of this chunk
        const float*  xbc = xs + buf * (KC * XP);
        const float4* abc = as4 + buf * (KC * 4);
        #pragma unroll
        for (int kk = 0; kk < 8; ++kk) {
            const int k = w * 8 + kk;
            const float xv0 = xbc[k * XP + lane];         // m = lane
            const float xv1 = xbc[k * XP + 32 + lane];    // m = lane + 32
            const u64 xd0 = pk2(xv0, xv0);
            const u64 xd1 = pk2(xv1, xv1);
            const ulonglong2* ap = (const ulonglong2*)(abc + k * 4);
            const ulonglong2 a01 = ap[0], a23 = ap[1];
            fma2(acc[0][0], xd0, a01.x); fma2(acc[1][0], xd1, a01.x);
            fma2(acc[0][1], xd0, a01.y); fma2(acc[1][1], xd1, a01.y);
            fma2(acc[0][2], xd0, a23.x); fma2(acc[1][2], xd1, a23.x);
            fma2(acc[0][3], xd0, a23.y); fma2(acc[1][3], xd1, a23.y);
            const ulonglong2 a45 = ap[2], a67 = ap[3];
            fma2(acc[0][4], xd0, a45.x); fma2(acc[1][4], xd1, a45.x);
            fma2(acc[0][5], xd0, a45.y); fma2(acc[1][5], xd1, a45.y);
            fma2(acc[0][6], xd0, a67.x); fma2(acc[1][6], xd1, a67.x);
            fma2(acc[0][7], xd0, a67.y); fma2(acc[1][7], xd1, a67.y);
        }

        if (c + 1 < NCH) {                      // stage chunk c+1
            float* xb = xs + ((c + 1) & 1) * (KC * XP);
            #pragma unroll
            for (int i = 0; i < 2; ++i)
                #pragma unroll
                for (int j = 0; j < 2; ++j) {
                    const int m = lm + 32 * i;
                    const int cc = lc + 32 * j;
                    xb[(cc + 0) * XP + m] = xr[i][j].x;
                    xb[(cc + 1) * XP + m] = xr[i][j].y;
                    xb[(cc + 2) * XP + m] = xr[i][j].z;
                    xb[(cc + 3) * XP + m] = xr[i][j].w;
                }
            as4[((c + 1) & 1) * 256 + tid] = ar;
        }
        __syncthreads();
    }

    // ---- cross-warp reduction (tredf aliases xs; lane-swizzled columns) ----
    #pragma unroll
    for (int mp = 0; mp < 2; ++mp) {
        const int m = lane + 32 * mp;
        const int base = w * 1024 + m * 16;
        #pragma unroll
        for (int rp = 0; rp < 8; ++rp) {
            const float2 f = up2(acc[mp][rp]);
            tredf[base + ((2 * rp     + lane) & 15)] = f.x;
            tredf[base + ((2 * rp + 1 + lane) & 15)] = f.y;
        }
    }
    __syncthreads();

    {   // final sum: thread -> (m = tid>>2, rank quad r0)
        const int m  = tid >> 2;
        const int r0 = (tid & 3) * 4;
        const int lw = m & 31;                  // writer's lane for this m
        float s[4];
        #pragma unroll
        for (int j = 0; j < 4; ++j) {
            const int cr = (r0 + j + lw) & 15;
            float v = 0.0f;
            #pragma unroll
            for (int w8 = 0; w8 < 8; ++w8)
                v += tredf[w8 * 1024 + m * 16 + cr];
            s[j] = v;
        }
        *(float4*)&g_tp[ks][mbase + m][r0] = make_float4(s[0], s[1], s[2], s[3]);
    }
}

// ---------------- phase 2 ----------------
__global__ __launch_bounds__(256, 3)
void lora_phase2(const float* __restrict__ B,
                 const float* __restrict__ bias,
                 float* __restrict__ out) {
    __shared__ u64 t_d[MSLAB][RANK];     // 16 KB, (t,t) duplicated

    const int tid   = threadIdx.x;
    const int oblk  = blockIdx.x & 3;
    const int mslab = blockIdx.x >> 2;
    const int o0    = oblk * OTPB + tid * 4;
    const int m0    = mslab * MSLAB;

    u64 bu[2][RANK];
    #pragma unroll
    for (int op = 0; op < 2; ++op) {
        float Bv0[RANK], Bv1[RANK];
        #pragma unroll
        for (int q = 0; q < 4; ++q) {
            *(float4*)&Bv0[4 * q] = *(const float4*)&B[(size_t)(o0 + 2 * op)     * RANK + 4 * q];
            *(float4*)&Bv1[4 * q] = *(const float4*)&B[(size_t)(o0 + 2 * op + 1) * RANK + 4 * q];
        }
        #pragma unroll
        for (int r = 0; r < RANK; ++r)
            bu[op][r] = pk2(Bv0[r], Bv1[r]);
    }
    const float4 bi4 = *(const float4*)&bias[o0];
    const u64 bias2[2] = { pk2(bi4.x, bi4.y), pk2(bi4.z, bi4.w) };

    // stage t slab: sum KSPLIT partials, store duplicated
    #pragma unroll
    for (int j = 0; j < 2; ++j) {
        const int idx = tid * 2 + j;      // 0..511
        const int m = idx >> 2, q = idx & 3;
        float4 s = make_float4(0, 0, 0, 0);
        #pragma unroll
        for (int sl = 0; sl < KSPLIT; ++sl) {
            const float4 v = *(const float4*)&g_tp[sl][m0 + m][4 * q];
            s.x += v.x; s.y += v.y; s.z += v.z; s.w += v.w;
        }
        t_d[m][4 * q + 0] = pk2(s.x, s.x);
        t_d[m][4 * q + 1] = pk2(s.y, s.y);
        t_d[m][4 * q + 2] = pk2(s.z, s.z);
        t_d[m][4 * q + 3] = pk2(s.w, s.w);
    }
    __syncthreads();

    // main loop: 2 m per iteration -> 4 independent FMA chains
    for (int m = 0; m < MSLAB; m += 2) {
        const ulonglong2* tp0 = (const ulonglong2*)&t_d[m][0];
        const ulonglong2* tp1 = (const ulonglong2*)&t_d[m + 1][0];
        u64 a0 = bias2[0], a1 = bias2[1];
        u64 b0 = bias2[0], b1 = bias2[1];
        #pragma unroll
        for (int rp = 0; rp < 8; ++rp) {
            const ulonglong2 t20 = tp0[rp];
            const ulonglong2 t21 = tp1[rp];
            fma2(a0, t20.x, bu[0][2 * rp]);
            fma2(a1, t20.x, bu[1][2 * rp]);
            fma2(b0, t21.x, bu[0][2 * rp]);
            fma2(b1, t21.x, bu[1][2 * rp]);
            fma2(a0, t20.y, bu[0][2 * rp + 1]);
            fma2(a1, t20.y, bu[1][2 * rp + 1]);
            fma2(b0, t21.y, bu[0][2 * rp + 1]);
            fma2(b1, t21.y, bu[1][2 * rp + 1]);
        }
        const float2 alo = up2(a0), ahi = up2(a1);
        const float2 blo = up2(b0), bhi = up2(b1);
        *(float4*)&out[(size_t)(m0 + m)     * OUT_F + o0] =
            make_float4(alo.x, alo.y, ahi.x, ahi.y);
        *(float4*)&out[(size_t)(m0 + m + 1) * OUT_F + o0] =
            make_float4(blo.x, blo.y, bhi.x, bhi.y);
    }
}

extern "C" void kernel_launch(void* const* d_in, const int* in_sizes, int n_in,
                              void* d_out, int out_size) {
    const float* x    = (const float*)d_in[0];   // [8192, 4096]
    const float* A    = (const float*)d_in[1];   // [16, 4096]
    const float* B    = (const float*)d_in[2];   // [4096, 16]
    const float* bias = (const float*)d_in[3];   // [4096]
    float* out = (float*)d_out;                  // [8192, 4096]

    prep_At<<<64, 256>>>(A);
    lora_phase1<<<(M_TOT / MT) * KSPLIT, 256>>>(x);
    lora_phase2<<<(OUT_F / OTPB) * (M_TOT / MSLAB), 256>>>(B, bias, out);
}

// round 10
// speedup vs baseline: 1.5173x; 1.5173x over previous
#include <cuda_runtime.h>
#include <cuda_bf16.h>
#include <cstdint>

// LoRA low-rank, 3-kernel pipeline (round 8 = R7 geometry at occupancy 2):
//   prep   : At[k][r] = 2 * A[r][k]
//   phase1 : tp[ks][m][r] = sum_{k in slice} x[m][k] * At[k][r]
//            2 m/lane (32 acc regs), full-line LDG, conflict-free pitch-65
//            transpose, occupancy 2 (NO register cap -> no spills).
//   phase2 : out[m][o] = sum_r (sum_ks tp) * B[o][r] + bias[o]
//            B in registers, t broadcast; 2-m unroll (4 ILP chains), occ 2.

#define IN_F   4096
#define OUT_F  4096
#define RANK   16
#define M_TOT  8192

#define KSPLIT 8
#define KRANGE (IN_F / KSPLIT)    // 512
#define MT     64                 // m rows per phase-1 block
#define KC     64                 // k chunk staged in smem
#define NCH    (KRANGE / KC)      // 8
#define XP     65                 // xs pitch: conflict-free both directions

#define OTPB   1024               // o columns per phase-2 block
#define MSLAB  128                // m rows per phase-2 block

__device__ __align__(16) float g_At[IN_F * RANK];            // 256 KB
__device__ __align__(16) float g_tp[KSPLIT][M_TOT][RANK];    // 4 MB partials

typedef unsigned long long u64;

__device__ __forceinline__ u64 pk2(float lo, float hi) {
    u64 r; asm("mov.b64 %0, {%1,%2};" : "=l"(r) : "f"(lo), "f"(hi)); return r;
}
__device__ __forceinline__ void fma2(u64 &d, u64 a, u64 b) {
    asm("fma.rn.f32x2 %0, %1, %2, %0;" : "+l"(d) : "l"(a), "l"(b));
}
__device__ __forceinline__ float2 up2(u64 v) {
    float2 f; asm("mov.b64 {%0,%1}, %2;" : "=f"(f.x), "=f"(f.y) : "l"(v)); return f;
}

// ---------------- prep: At = 2*A^T, coalesced STG.128 ----------------
__global__ void prep_At(const float* __restrict__ A) {
    const int i  = blockIdx.x * 256 + threadIdx.x;   // 16384
    const int k  = i >> 2;
    const int rq = i & 3;
    float4 v;
    v.x = 2.0f * A[(size_t)(4 * rq + 0) * IN_F + k];
    v.y = 2.0f * A[(size_t)(4 * rq + 1) * IN_F + k];
    v.z = 2.0f * A[(size_t)(4 * rq + 2) * IN_F + k];
    v.w = 2.0f * A[(size_t)(4 * rq + 3) * IN_F + k];
    ((float4*)g_At)[k * 4 + rq] = v;
}

// ---------------- phase 1 ----------------
// smem: [0,33280) xs[2][KC][XP] floats ; [33280,41472) as4[2][KC*4] float4
//       tredf[8][64][16] floats (32768 B) aliases xs after the k-loop.
__global__ __launch_bounds__(256, 2)
void lora_phase1(const float* __restrict__ x) {
    __shared__ __align__(16) char sraw[41472];
    float*  xs    = (float*)sraw;
    float4* as4   = (float4*)(sraw + 33280);
    float*  tredf = (float*)sraw;

    const int tid  = threadIdx.x;
    const int lane = tid & 31;
    const int w    = tid >> 5;                  // 8 warps
    const int ks   = blockIdx.x & (KSPLIT - 1);
    const int mt   = blockIdx.x >> 3;           // 0..127
    const int mbase = mt * MT;
    const int k0    = ks * KRANGE;

    // full-line LDG mapping: lanes 0..7 cover one whole 128B line of a row
    const int lm = tid >> 3;                    // 0..31 (row in 32-row group)
    const int lc = (tid & 7) * 4;               // col floats within 32-col half
    const float* xg = x + (size_t)(mbase + lm) * IN_F + k0 + lc;

    u64 acc[2][8];
    #pragma unroll
    for (int mp = 0; mp < 2; ++mp)
        #pragma unroll
        for (int rp = 0; rp < 8; ++rp) acc[mp][rp] = 0ull;

    float4 xr[2][2], ar;

    // prologue: chunk 0 (rows lm, lm+32; col halves lc, lc+32)
    #pragma unroll
    for (int i = 0; i < 2; ++i)
        #pragma unroll
        for (int j = 0; j < 2; ++j)
            xr[i][j] = *(const float4*)(xg + (size_t)(32 * i) * IN_F + 32 * j);
    ar = ((const float4*)g_At)[k0 * 4 + tid];

    #pragma unroll
    for (int i = 0; i < 2; ++i)
        #pragma unroll
        for (int j = 0; j < 2; ++j) {
            const int m = lm + 32 * i;
            const int c = lc + 32 * j;
            xs[(c + 0) * XP + m] = xr[i][j].x;
            xs[(c + 1) * XP + m] = xr[i][j].y;
            xs[(c + 2) * XP + m] = xr[i][j].z;
            xs[(c + 3) * XP + m] = xr[i][j].w;
        }
    as4[tid] = ar;
    __syncthreads();

    for (int c = 0; c < NCH; ++c) {
        const int buf = c & 1;

        if (c + 1 < NCH) {                      // prefetch chunk c+1
            const int kc1 = (c + 1) * KC;
            #pragma unroll
            for (int i = 0; i < 2; ++i)
                #pragma unroll
                for (int j = 0; j < 2; ++j)
                    xr[i][j] = *(const float4*)(xg + kc1 + (size_t)(32 * i) * IN_F + 32 * j);
            ar = ((const float4*)g_At)[(k0 + kc1) * 4 + tid];
        }

        // compute: warp w covers k = w*8 .. w*8+7 of this chunk
        const float*  xbc = xs + buf * (KC * XP);
        const float4* abc = as4 + buf * (KC * 4);
        #pragma unroll
        for (int kk = 0; kk < 8; ++kk) {
            const int k = w * 8 + kk;
            const float xv0 = xbc[k * XP + lane];         // m = lane
            const float xv1 = xbc[k * XP + 32 + lane];    // m = lane + 32
            const u64 xd0 = pk2(xv0, xv0);
            const u64 xd1 = pk2(xv1, xv1);
            const ulonglong2* ap = (const ulonglong2*)(abc + k * 4);
            const ulonglong2 a01 = ap[0], a23 = ap[1];
            fma2(acc[0][0], xd0, a01.x); fma2(acc[1][0], xd1, a01.x);
            fma2(acc[0][1], xd0, a01.y); fma2(acc[1][1], xd1, a01.y);
            fma2(acc[0][2], xd0, a23.x); fma2(acc[1][2], xd1, a23.x);
            fma2(acc[0][3], xd0, a23.y); fma2(acc[1][3], xd1, a23.y);
            const ulonglong2 a45 = ap[2], a67 = ap[3];
            fma2(acc[0][4], xd0, a45.x); fma2(acc[1][4], xd1, a45.x);
            fma2(acc[0][5], xd0, a45.y); fma2(acc[1][5], xd1, a45.y);
            fma2(acc[0][6], xd0, a67.x); fma2(acc[1][6], xd1, a67.x);
            fma2(acc[0][7], xd0, a67.y); fma2(acc[1][7], xd1, a67.y);
        }

        if (c + 1 < NCH) {                      // stage chunk c+1
            float* xb = xs + ((c + 1) & 1) * (KC * XP);
            #pragma unroll
            for (int i = 0; i < 2; ++i)
                #pragma unroll
                for (int j = 0; j < 2; ++j) {
                    const int m = lm + 32 * i;
                    const int cc = lc + 32 * j;
                    xb[(cc + 0) * XP + m] = xr[i][j].x;
                    xb[(cc + 1) * XP + m] = xr[i][j].y;
                    xb[(cc + 2) * XP + m] = xr[i][j].z;
                    xb[(cc + 3) * XP + m] = xr[i][j].w;
                }
            as4[((c + 1) & 1) * 256 + tid] = ar;
        }
        __syncthreads();
    }

    // ---- cross-warp reduction (tredf aliases xs; lane-swizzled columns) ----
    #pragma unroll
    for (int mp = 0; mp < 2; ++mp) {
        const int m = lane + 32 * mp;
        const int base = w * 1024 + m * 16;
        #pragma unroll
        for (int rp = 0; rp < 8; ++rp) {
            const float2 f = up2(acc[mp][rp]);
            tredf[base + ((2 * rp     + lane) & 15)] = f.x;
            tredf[base + ((2 * rp + 1 + lane) & 15)] = f.y;
        }
    }
    __syncthreads();

    {   // final sum: thread -> (m = tid>>2, rank quad r0)
        const int m  = tid >> 2;
        const int r0 = (tid & 3) * 4;
        const int lw = m & 31;                  // writer's lane for this m
        float s[4];
        #pragma unroll
        for (int j = 0; j < 4; ++j) {
            const int cr = (r0 + j + lw) & 15;
            float v = 0.0f;
            #pragma unroll
            for (int w8 = 0; w8 < 8; ++w8)
                v += tredf[w8 * 1024 + m * 16 + cr];
            s[j] = v;
        }
        *(float4*)&g_tp[ks][mbase + m][r0] = make_float4(s[0], s[1], s[2], s[3]);
    }
}

// ---------------- phase 2 ----------------
__global__ __launch_bounds__(256, 2)
void lora_phase2(const float* __restrict__ B,
                 const float* __restrict__ bias,
                 float* __restrict__ out) {
    __shared__ u64 t_d[MSLAB][RANK];     // 16 KB, (t,t) duplicated

    const int tid   = threadIdx.x;
    const int oblk  = blockIdx.x & 3;
    const int mslab = blockIdx.x >> 2;
    const int o0    = oblk * OTPB + tid * 4;
    const int m0    = mslab * MSLAB;

    u64 bu[2][RANK];
    #pragma unroll
    for (int op = 0; op < 2; ++op) {
        float Bv0[RANK], Bv1[RANK];
        #pragma unroll
        for (int q = 0; q < 4; ++q) {
            *(float4*)&Bv0[4 * q] = *(const float4*)&B[(size_t)(o0 + 2 * op)     * RANK + 4 * q];
            *(float4*)&Bv1[4 * q] = *(const float4*)&B[(size_t)(o0 + 2 * op + 1) * RANK + 4 * q];
        }
        #pragma unroll
        for (int r = 0; r < RANK; ++r)
            bu[op][r] = pk2(Bv0[r], Bv1[r]);
    }
    const float4 bi4 = *(const float4*)&bias[o0];
    const u64 bias2[2] = { pk2(bi4.x, bi4.y), pk2(bi4.z, bi4.w) };

    // stage t slab: sum KSPLIT partials, store duplicated
    #pragma unroll
    for (int j = 0; j < 2; ++j) {
        const int idx = tid * 2 + j;      // 0..511
        const int m = idx >> 2, q = idx & 3;
        float4 s = make_float4(0, 0, 0, 0);
        #pragma unroll
        for (int sl = 0; sl < KSPLIT; ++sl) {
            const float4 v = *(const float4*)&g_tp[sl][m0 + m][4 * q];
            s.x += v.x; s.y += v.y; s.z += v.z; s.w += v.w;
        }
        t_d[m][4 * q + 0] = pk2(s.x, s.x);
        t_d[m][4 * q + 1] = pk2(s.y, s.y);
        t_d[m][4 * q + 2] = pk2(s.z, s.z);
        t_d[m][4 * q + 3] = pk2(s.w, s.w);
    }
    __syncthreads();

    // main loop: 2 m per iteration -> 4 independent FMA chains
    for (int m = 0; m < MSLAB; m += 2) {
        const ulonglong2* tp0 = (const ulonglong2*)&t_d[m][0];
        const ulonglong2* tp1 = (const ulonglong2*)&t_d[m + 1][0];
        u64 a0 = bias2[0], a1 = bias2[1];
        u64 b0 = bias2[0], b1 = bias2[1];
        #pragma unroll
        for (int rp = 0; rp < 8; ++rp) {
            const ulonglong2 t20 = tp0[rp];
            const ulonglong2 t21 = tp1[rp];
            fma2(a0, t20.x, bu[0][2 * rp]);
            fma2(a1, t20.x, bu[1][2 * rp]);
            fma2(b0, t21.x, bu[0][2 * rp]);
            fma2(b1, t21.x, bu[1][2 * rp]);
            fma2(a0, t20.y, bu[0][2 * rp + 1]);
            fma2(a1, t20.y, bu[1][2 * rp + 1]);
            fma2(b0, t21.y, bu[0][2 * rp + 1]);
            fma2(b1, t21.y, bu[1][2 * rp + 1]);
        }
        const float2 alo = up2(a0), ahi = up2(a1);
        const float2 blo = up2(b0), bhi = up2(b1);
        *(float4*)&out[(size_t)(m0 + m)     * OUT_F + o0] =
            make_float4(alo.x, alo.y, ahi.x, ahi.y);
        *(float4*)&out[(size_t)(m0 + m + 1) * OUT_F + o0] =
            make_float4(blo.x, blo.y, bhi.x, bhi.y);
    }
}

extern "C" void kernel_launch(void* const* d_in, const int* in_sizes, int n_in,
                              void* d_out, int out_size) {
    const float* x    = (const float*)d_in[0];   // [8192, 4096]
    const float* A    = (const float*)d_in[1];   // [16, 4096]
    const float* B    = (const float*)d_in[2];   // [4096, 16]
    const float* bias = (const float*)d_in[3];   // [4096]
    float* out = (float*)d_out;                  // [8192, 4096]

    prep_At<<<64, 256>>>(A);
    lora_phase1<<<(M_TOT / MT) * KSPLIT, 256>>>(x);
    lora_phase2<<<(OUT_F / OTPB) * (M_TOT / MSLAB), 256>>>(B, bias, out);
}

// round 12
// speedup vs baseline: 1.5553x; 1.0250x over previous
#include <cuda_runtime.h>
#include <cuda_bf16.h>
#include <cstdint>

// LoRA low-rank, 2-kernel pipeline (round 10 = R8 with prep folded into phase1):
//   phase1 : tp[ks][m][r] = sum_{k in slice} x[m][k] * 2*A[r][k]
//            A transposed on the fly into smem (L2-resident), no prep kernel.
//   phase2 : out[m][o] = sum_r (sum_ks tp) * B[o][r] + bias[o]

#define IN_F   4096
#define OUT_F  4096
#define RANK   16
#define M_TOT  8192

#define KSPLIT 8
#define KRANGE (IN_F / KSPLIT)    // 512
#define MT     64                 // m rows per phase-1 block
#define KC     64                 // k chunk staged in smem
#define NCH    (KRANGE / KC)      // 8
#define XP     65                 // xs pitch: conflict-free both directions

#define OTPB   1024               // o columns per phase-2 block
#define MSLAB  128                // m rows per phase-2 block

__device__ __align__(16) float g_tp[KSPLIT][M_TOT][RANK];    // 4 MB partials

typedef unsigned long long u64;

__device__ __forceinline__ u64 pk2(float lo, float hi) {
    u64 r; asm("mov.b64 %0, {%1,%2};" : "=l"(r) : "f"(lo), "f"(hi)); return r;
}
__device__ __forceinline__ void fma2(u64 &d, u64 a, u64 b) {
    asm("fma.rn.f32x2 %0, %1, %2, %0;" : "+l"(d) : "l"(a), "l"(b));
}
__device__ __forceinline__ float2 up2(u64 v) {
    float2 f; asm("mov.b64 {%0,%1}, %2;" : "=f"(f.x), "=f"(f.y) : "l"(v)); return f;
}

// ---------------- phase 1 ----------------
// smem: [0,33280) xs[2][KC][XP] floats ; [33280,41472) as4[2][KC*4] float4
//       tredf[8][64][16] floats (32768 B) aliases xs after the k-loop.
__global__ __launch_bounds__(256, 2)
void lora_phase1(const float* __restrict__ x,
                 const float* __restrict__ A) {
    __shared__ __align__(16) char sraw[41472];
    float*  xs    = (float*)sraw;
    float4* as4   = (float4*)(sraw + 33280);
    float*  tredf = (float*)sraw;

    const int tid  = threadIdx.x;
    const int lane = tid & 31;
    const int w    = tid >> 5;                  // 8 warps
    const int ks   = blockIdx.x & (KSPLIT - 1);
    const int mt   = blockIdx.x >> 3;           // 0..127
    const int mbase = mt * MT;
    const int k0    = ks * KRANGE;

    // full-line LDG mapping: lanes 0..7 cover one whole 128B line of a row
    const int lm = tid >> 3;                    // 0..31 (row in 32-row group)
    const int lc = (tid & 7) * 4;               // col floats within 32-col half
    const float* xg = x + (size_t)(mbase + lm) * IN_F + k0 + lc;

    // A staging mapping: thread -> (k-in-chunk, rank-quad)
    const int ka = tid >> 2;                    // 0..63
    const int rq = tid & 3;                     // 0..3
    const float* Ag = A + (size_t)(4 * rq) * IN_F + k0 + ka;

    u64 acc[2][8];
    #pragma unroll
    for (int mp = 0; mp < 2; ++mp)
        #pragma unroll
        for (int rp = 0; rp < 8; ++rp) acc[mp][rp] = 0ull;

    float4 xr[2][2], ar;

    // prologue: chunk 0 (rows lm, lm+32; col halves lc, lc+32)
    #pragma unroll
    for (int i = 0; i < 2; ++i)
        #pragma unroll
        for (int j = 0; j < 2; ++j)
            xr[i][j] = *(const float4*)(xg + (size_t)(32 * i) * IN_F + 32 * j);
    ar.x = Ag[0];
    ar.y = Ag[(size_t)1 * IN_F];
    ar.z = Ag[(size_t)2 * IN_F];
    ar.w = Ag[(size_t)3 * IN_F];

    #pragma unroll
    for (int i = 0; i < 2; ++i)
        #pragma unroll
        for (int j = 0; j < 2; ++j) {
            const int m = lm + 32 * i;
            const int c = lc + 32 * j;
            xs[(c + 0) * XP + m] = xr[i][j].x;
            xs[(c + 1) * XP + m] = xr[i][j].y;
            xs[(c + 2) * XP + m] = xr[i][j].z;
            xs[(c + 3) * XP + m] = xr[i][j].w;
        }
    as4[tid] = make_float4(2.0f * ar.x, 2.0f * ar.y, 2.0f * ar.z, 2.0f * ar.w);
    __syncthreads();

    for (int c = 0; c < NCH; ++c) {
        const int buf = c & 1;

        if (c + 1 < NCH) {                      // prefetch chunk c+1
            const int kc1 = (c + 1) * KC;
            #pragma unroll
            for (int i = 0; i < 2; ++i)
                #pragma unroll
                for (int j = 0; j < 2; ++j)
                    xr[i][j] = *(const float4*)(xg + kc1 + (size_t)(32 * i) * IN_F + 32 * j);
            ar.x = Ag[kc1];
            ar.y = Ag[kc1 + (size_t)1 * IN_F];
            ar.z = Ag[kc1 + (size_t)2 * IN_F];
            ar.w = Ag[kc1 + (size_t)3 * IN_F];
        }

        // compute: warp w covers k = w*8 .. w*8+7 of this chunk
        const float*  xbc = xs + buf * (KC * XP);
        const float4* abc = as4 + buf * (KC * 4);
        #pragma unroll
        for (int kk = 0; kk < 8; ++kk) {
            const int k = w * 8 + kk;
            const float xv0 = xbc[k * XP + lane];         // m = lane
            const float xv1 = xbc[k * XP + 32 + lane];    // m = lane + 32
            const u64 xd0 = pk2(xv0, xv0);
            const u64 xd1 = pk2(xv1, xv1);
            const ulonglong2* ap = (const ulonglong2*)(abc + k * 4);
            const ulonglong2 a01 = ap[0], a23 = ap[1];
            fma2(acc[0][0], xd0, a01.x); fma2(acc[1][0], xd1, a01.x);
            fma2(acc[0][1], xd0, a01.y); fma2(acc[1][1], xd1, a01.y);
            fma2(acc[0][2], xd0, a23.x); fma2(acc[1][2], xd1, a23.x);
            fma2(acc[0][3], xd0, a23.y); fma2(acc[1][3], xd1, a23.y);
            const ulonglong2 a45 = ap[2], a67 = ap[3];
            fma2(acc[0][4], xd0, a45.x); fma2(acc[1][4], xd1, a45.x);
            fma2(acc[0][5], xd0, a45.y); fma2(acc[1][5], xd1, a45.y);
            fma2(acc[0][6], xd0, a67.x); fma2(acc[1][6], xd1, a67.x);
            fma2(acc[0][7], xd0, a67.y); fma2(acc[1][7], xd1, a67.y);
        }

        if (c + 1 < NCH) {                      // stage chunk c+1
            float* xb = xs + ((c + 1) & 1) * (KC * XP);
            #pragma unroll
            for (int i = 0; i < 2; ++i)
                #pragma unroll
                for (int j = 0; j < 2; ++j) {
                    const int m = lm + 32 * i;
                    const int cc = lc + 32 * j;
                    xb[(cc + 0) * XP + m] = xr[i][j].x;
                    xb[(cc + 1) * XP + m] = xr[i][j].y;
                    xb[(cc + 2) * XP + m] = xr[i][j].z;
                    xb[(cc + 3) * XP + m] = xr[i][j].w;
                }
            as4[((c + 1) & 1) * 256 + tid] =
                make_float4(2.0f * ar.x, 2.0f * ar.y, 2.0f * ar.z, 2.0f * ar.w);
        }
        __syncthreads();
    }

    // ---- cross-warp reduction (tredf aliases xs; lane-swizzled columns) ----
    #pragma unroll
    for (int mp = 0; mp < 2; ++mp) {
        const int m = lane + 32 * mp;
        const int base = w * 1024 + m * 16;
        #pragma unroll
        for (int rp = 0; rp < 8; ++rp) {
            const float2 f = up2(acc[mp][rp]);
            tredf[base + ((2 * rp     + lane) & 15)] = f.x;
            tredf[base + ((2 * rp + 1 + lane) & 15)] = f.y;
        }
    }
    __syncthreads();

    {   // final sum: thread -> (m = tid>>2, rank quad r0)
        const int m  = tid >> 2;
        const int r0 = (tid & 3) * 4;
        const int lw = m & 31;                  // writer's lane for this m
        float s[4];
        #pragma unroll
        for (int j = 0; j < 4; ++j) {
            const int cr = (r0 + j + lw) & 15;
            float v = 0.0f;
            #pragma unroll
            for (int w8 = 0; w8 < 8; ++w8)
                v += tredf[w8 * 1024 + m * 16 + cr];
            s[j] = v;
        }
        *(float4*)&g_tp[ks][mbase + m][r0] = make_float4(s[0], s[1], s[2], s[3]);
    }
}

// ---------------- phase 2 ----------------
__global__ __launch_bounds__(256, 2)
void lora_phase2(const float* __restrict__ B,
                 const float* __restrict__ bias,
                 float* __restrict__ out) {
    __shared__ u64 t_d[MSLAB][RANK];     // 16 KB, (t,t) duplicated

    const int tid   = threadIdx.x;
    const int oblk  = blockIdx.x & 3;
    const int mslab = blockIdx.x >> 2;
    const int o0    = oblk * OTPB + tid * 4;
    const int m0    = mslab * MSLAB;

    u64 bu[2][RANK];
    #pragma unroll
    for (int op = 0; op < 2; ++op) {
        float Bv0[RANK], Bv1[RANK];
        #pragma unroll
        for (int q = 0; q < 4; ++q) {
            *(float4*)&Bv0[4 * q] = *(const float4*)&B[(size_t)(o0 + 2 * op)     * RANK + 4 * q];
            *(float4*)&Bv1[4 * q] = *(const float4*)&B[(size_t)(o0 + 2 * op + 1) * RANK + 4 * q];
        }
        #pragma unroll
        for (int r = 0; r < RANK; ++r)
            bu[op][r] = pk2(Bv0[r], Bv1[r]);
    }
    const float4 bi4 = *(const float4*)&bias[o0];
    const u64 bias2[2] = { pk2(bi4.x, bi4.y), pk2(bi4.z, bi4.w) };

    // stage t slab: sum KSPLIT partials, store duplicated
    #pragma unroll
    for (int j = 0; j < 2; ++j) {
        const int idx = tid * 2 + j;      // 0..511
        const int m = idx >> 2, q = idx & 3;
        float4 s = make_float4(0, 0, 0, 0);
        #pragma unroll
        for (int sl = 0; sl < KSPLIT; ++sl) {
            const float4 v = *(const float4*)&g_tp[sl][m0 + m][4 * q];
            s.x += v.x; s.y += v.y; s.z += v.z; s.w += v.w;
        }
        t_d[m][4 * q + 0] = pk2(s.x, s.x);
        t_d[m][4 * q + 1] = pk2(s.y, s.y);
        t_d[m][4 * q + 2] = pk2(s.z, s.z);
        t_d[m][4 * q + 3] = pk2(s.w, s.w);
    }
    __syncthreads();

    // main loop: 2 m per iteration -> 4 independent FMA chains
    for (int m = 0; m < MSLAB; m += 2) {
        const ulonglong2* tp0 = (const ulonglong2*)&t_d[m][0];
        const ulonglong2* tp1 = (const ulonglong2*)&t_d[m + 1][0];
        u64 a0 = bias2[0], a1 = bias2[1];
        u64 b0 = bias2[0], b1 = bias2[1];
        #pragma unroll
        for (int rp = 0; rp < 8; ++rp) {
            const ulonglong2 t20 = tp0[rp];
            const ulonglong2 t21 = tp1[rp];
            fma2(a0, t20.x, bu[0][2 * rp]);
            fma2(a1, t20.x, bu[1][2 * rp]);
            fma2(b0, t21.x, bu[0][2 * rp]);
            fma2(b1, t21.x, bu[1][2 * rp]);
            fma2(a0, t20.y, bu[0][2 * rp + 1]);
            fma2(a1, t20.y, bu[1][2 * rp + 1]);
            fma2(b0, t21.y, bu[0][2 * rp + 1]);
            fma2(b1, t21.y, bu[1][2 * rp + 1]);
        }
        const float2 alo = up2(a0), ahi = up2(a1);
        const float2 blo = up2(b0), bhi = up2(b1);
        *(float4*)&out[(size_t)(m0 + m)     * OUT_F + o0] =
            make_float4(alo.x, alo.y, ahi.x, ahi.y);
        *(float4*)&out[(size_t)(m0 + m + 1) * OUT_F + o0] =
            make_float4(blo.x, blo.y, bhi.x, bhi.y);
    }
}

extern "C" void kernel_launch(void* const* d_in, const int* in_sizes, int n_in,
                              void* d_out, int out_size) {
    const float* x    = (const float*)d_in[0];   // [8192, 4096]
    const float* A    = (const float*)d_in[1];   // [16, 4096]
    const float* B    = (const float*)d_in[2];   // [4096, 16]
    const float* bias = (const float*)d_in[3];   // [4096]
    float* out = (float*)d_out;                  // [8192, 4096]

    lora_phase1<<<(M_TOT / MT) * KSPLIT, 256>>>(x, A);
    lora_phase2<<<(OUT_F / OTPB) * (M_TOT / MSLAB), 256>>>(B, bias, out);
}